// round 10
// baseline (speedup 1.0000x reference)
#include <cuda_runtime.h>
#include <cuda_bf16.h>

#define N_NODES  8192
#define ROUNDS   9            // rounds producing inflow_2 .. inflow_10
#define CAP      128          // bucket capacity (Poisson(32): P(>127) ~ 1e-40)
#define CSC_OFF  4096         // float offset of CSC bucket inside an output row
#define FGRID    64
#define FBLOCK   1024         // FGRID*FBLOCK == 65536 == e4
#define WORKERS  8            // blocks that run the rounds (8*1024 = N_NODES)
#define RBLOCK   256

// small persistent scratch only
__device__ unsigned int g_bar[16];          // monotonic barrier counters
__device__ float        g_buf[2][N_NODES];  // double-buffered inflow
__device__ int          g_csr_cnt[N_NODES];
__device__ int          g_csc_cnt[N_NODES];

__device__ __forceinline__ float ldcg_f(const float* p) {
    float v;
    asm volatile("ld.global.cg.f32 %0, [%1];" : "=f"(v) : "l"(p));
    return v;
}

// grid barrier with parametric arrival count (monotonic; reset by k_rows)
__device__ __forceinline__ void grid_barrier(int b, unsigned int expected) {
    __syncthreads();
    if (threadIdx.x == 0) {
        __threadfence();
        atomicAdd(&g_bar[b], 1u);
        volatile unsigned int* p = &g_bar[b];
        while (*p < expected) __nanosleep(32);
        __threadfence();
    }
    __syncthreads();
}

__global__ void __launch_bounds__(FBLOCK, 1)
k_flow(const int*   __restrict__ rows,
       const int*   __restrict__ cols,
       const float* __restrict__ values,
       const float* __restrict__ demands,
       float*       __restrict__ out,
       int e4)
{
    __shared__ float s_adj[N_NODES];          // 32 KB
    __shared__ float s_d[N_NODES];            // 32 KB
    const int tid = blockIdx.x * FBLOCK + threadIdx.x;   // 0..65535
    const int nth = FGRID * FBLOCK;

    // ---- phase 0a: reset counters/buffers ----
    for (int i = tid; i < N_NODES; i += nth) {
        g_csr_cnt[i] = 0;
        g_csc_cnt[i] = 0;
        g_buf[0][i]  = 0.0f;                  // inflow_1 = 0
    }
    grid_barrier(0, FGRID);                   // zeroing before any bucketing

    // ---- phase 0b: bucket this thread's 4 edges ----
    if (tid < e4) {
        int4   r4 = __ldg(((const int4*)rows)   + tid);
        int4   c4 = __ldg(((const int4*)cols)   + tid);
        float4 v4 = __ldg(((const float4*)values) + tid);
        int s;
        // CSR: (col, val) at floats [0, 2*CAP) of output row r
        s = atomicAdd(&g_csr_cnt[r4.x], 1);
        if (s < CAP) *(float2*)(out + (size_t)r4.x * N_NODES + 2 * s) = make_float2(__int_as_float(c4.x), v4.x);
        s = atomicAdd(&g_csr_cnt[r4.y], 1);
        if (s < CAP) *(float2*)(out + (size_t)r4.y * N_NODES + 2 * s) = make_float2(__int_as_float(c4.y), v4.y);
        s = atomicAdd(&g_csr_cnt[r4.z], 1);
        if (s < CAP) *(float2*)(out + (size_t)r4.z * N_NODES + 2 * s) = make_float2(__int_as_float(c4.z), v4.z);
        s = atomicAdd(&g_csr_cnt[r4.w], 1);
        if (s < CAP) *(float2*)(out + (size_t)r4.w * N_NODES + 2 * s) = make_float2(__int_as_float(c4.w), v4.w);
        // CSC: (row, val) at floats [CSC_OFF, CSC_OFF+2*CAP) of output row c
        s = atomicAdd(&g_csc_cnt[c4.x], 1);
        if (s < CAP) *(float2*)(out + (size_t)c4.x * N_NODES + CSC_OFF + 2 * s) = make_float2(__int_as_float(r4.x), v4.x);
        s = atomicAdd(&g_csc_cnt[c4.y], 1);
        if (s < CAP) *(float2*)(out + (size_t)c4.y * N_NODES + CSC_OFF + 2 * s) = make_float2(__int_as_float(r4.y), v4.y);
        s = atomicAdd(&g_csc_cnt[c4.z], 1);
        if (s < CAP) *(float2*)(out + (size_t)c4.z * N_NODES + CSC_OFF + 2 * s) = make_float2(__int_as_float(r4.z), v4.z);
        s = atomicAdd(&g_csc_cnt[c4.w], 1);
        if (s < CAP) *(float2*)(out + (size_t)c4.w * N_NODES + CSC_OFF + 2 * s) = make_float2(__int_as_float(r4.w), v4.w);
    }

    grid_barrier(1, FGRID);                   // all buckets complete

    if (blockIdx.x >= WORKERS) return;        // only 8 blocks run the rounds

    // cache demands in smem once
    for (int i = threadIdx.x; i < N_NODES; i += FBLOCK)
        s_d[i] = __ldg(&demands[i]);
    // no sync needed yet: s_d consumed only after the adj-build sync below

    // one thread per column
    const int col  = blockIdx.x * FBLOCK + threadIdx.x;   // 0..8191
    const int ncol = min(g_csc_cnt[col], CAP);
    const float4* ep4 = (const float4*)(out + (size_t)col * N_NODES + CSC_OFF);

    // ---- rounds: it reads R = inflow_{it+1}, writes W = inflow_{it+2} ----
    for (int it = 0; it < ROUNDS; ++it) {
        const float* R = g_buf[it & 1];
        float*       W = g_buf[(it + 1) & 1];

        // adj_{it+1} into smem (coalesced; 8 blocks -> 8x less L2 traffic)
        for (int i = threadIdx.x; i < N_NODES; i += FBLOCK)
            s_adj[i] = fmaxf(ldcg_f(&R[i]) - s_d[i], 0.0f);
        __syncthreads();

        // gather this column's edges: 2 (row,val) pairs per float4 load
        float acc = 0.0f;
        #pragma unroll 4
        for (int e = 0; e < ncol; e += 2) {
            float4 p = __ldg(ep4 + (e >> 1));
            acc += p.y * s_adj[__float_as_int(p.x)];
            if (e + 1 < ncol)
                acc += p.w * s_adj[__float_as_int(p.z)];
        }
        W[col] = acc;                          // each node written exactly once

        if (it < ROUNDS - 1) grid_barrier(2 + it, WORKERS);
        // last round: kernel boundary is the sync; inflow_10 = g_buf[1]
    }
}

// One block per output row: stage CSR bucket, build row in smem, stream out.
__global__ void __launch_bounds__(RBLOCK)
k_rows(const float* __restrict__ demands,
       float*       __restrict__ out)
{
    __shared__ float  srow[N_NODES];          // 32 KB
    __shared__ float2 sbuck[CAP];             // 1 KB
    const int row = blockIdx.x;

    if (row == 0 && threadIdx.x < 16)         // reset barriers for next replay
        g_bar[threadIdx.x] = 0u;

    const int n = min(g_csr_cnt[row], CAP);
    const float* rowp = out + (size_t)row * N_NODES;

    for (int e = threadIdx.x; e < n; e += RBLOCK)
        sbuck[e] = *(const float2*)(rowp + 2 * e);
    for (int i = threadIdx.x; i < N_NODES; i += RBLOCK)
        srow[i] = 0.0f;
    __syncthreads();

    // adj_10[row] = relu(inflow_10[row] - d[row]);  inflow_10 = g_buf[1]
    const float a = fmaxf(g_buf[1][row] - __ldg(&demands[row]), 0.0f);

    for (int e = threadIdx.x; e < n; e += RBLOCK)
        atomicAdd(&srow[__float_as_int(sbuck[e].x)], sbuck[e].y * a);
    __syncthreads();

    float4*       dst = (float4*)(out + (size_t)row * N_NODES);
    const float4* src = (const float4*)srow;
    for (int i = threadIdx.x; i < N_NODES / 4; i += RBLOCK)
        dst[i] = src[i];
}

extern "C" void kernel_launch(void* const* d_in, const int* in_sizes, int n_in,
                              void* d_out, int out_size) {
    const float* values  = (const float*)d_in[0];
    const float* demands = (const float*)d_in[1];
    const int*   rows    = (const int*)d_in[2];
    const int*   cols    = (const int*)d_in[3];
    float*       out     = (float*)d_out;

    const int E  = in_sizes[0];   // 262144
    const int e4 = E / 4;         // 65536

    k_flow<<<FGRID, FBLOCK>>>(rows, cols, values, demands, out, e4);
    k_rows<<<N_NODES, RBLOCK>>>(demands, out);
}

// round 11
// speedup vs baseline: 1.9354x; 1.9354x over previous
#include <cuda_runtime.h>
#include <cuda_bf16.h>

#define N_NODES  8192
#define ROUNDS   9            // rounds producing inflow_2 .. inflow_10
#define CAP      128          // bucket capacity (Poisson(32): P(>127) ~ 1e-40)
#define CSC_OFF  4096         // float offset of CSC bucket inside an output row
#define FGRID    64
#define FBLOCK   1024         // FGRID*FBLOCK == 65536 == e4 == 8*N_NODES
#define RBLOCK   256

// small persistent scratch (zero-initialized at module load; k_clean/k_rows
// restore the zeroed state after every pass -> deterministic graph replays)
__device__ unsigned int g_bar[16];          // monotonic barrier counters
__device__ float        g_buf[2][N_NODES];  // double-buffered inflow
__device__ int          g_csr_cnt[N_NODES];
__device__ int          g_csc_cnt[N_NODES];

__device__ __forceinline__ float ldcg_f(const float* p) {
    float v;
    asm volatile("ld.global.cg.f32 %0, [%1];" : "=f"(v) : "l"(p));
    return v;
}

// grid-wide barrier among FGRID blocks (monotonic counters; reset by k_rows)
__device__ __forceinline__ void grid_barrier(int b) {
    __syncthreads();
    if (threadIdx.x == 0) {
        __threadfence();
        atomicAdd(&g_bar[b], 1u);
        volatile unsigned int* p = &g_bar[b];
        while (*p < FGRID) __nanosleep(32);
        __threadfence();
    }
    __syncthreads();
}

// Bucket edges by row (CSR -> k_rows) and by column (CSC -> k_rounds), both
// stored inside d_out (scratch until k_rows rewrites it). Counters arrive
// pre-zeroed (module load / k_clean), so no barriers are needed here.
__global__ void __launch_bounds__(FBLOCK, 1)
k_bucket(const int*   __restrict__ rows,
         const int*   __restrict__ cols,
         const float* __restrict__ values,
         float*       __restrict__ out,
         int e4)
{
    const int tid = blockIdx.x * FBLOCK + threadIdx.x;   // 0..65535
    if (tid >= e4) return;

    int4   r4 = __ldg(((const int4*)rows)   + tid);
    int4   c4 = __ldg(((const int4*)cols)   + tid);
    float4 v4 = __ldg(((const float4*)values) + tid);
    int s;
    // CSR: (col, val) at floats [0, 2*CAP) of output row r
    s = atomicAdd(&g_csr_cnt[r4.x], 1);
    if (s < CAP) *(float2*)(out + (size_t)r4.x * N_NODES + 2 * s) = make_float2(__int_as_float(c4.x), v4.x);
    s = atomicAdd(&g_csr_cnt[r4.y], 1);
    if (s < CAP) *(float2*)(out + (size_t)r4.y * N_NODES + 2 * s) = make_float2(__int_as_float(c4.y), v4.y);
    s = atomicAdd(&g_csr_cnt[r4.z], 1);
    if (s < CAP) *(float2*)(out + (size_t)r4.z * N_NODES + 2 * s) = make_float2(__int_as_float(c4.z), v4.z);
    s = atomicAdd(&g_csr_cnt[r4.w], 1);
    if (s < CAP) *(float2*)(out + (size_t)r4.w * N_NODES + 2 * s) = make_float2(__int_as_float(c4.w), v4.w);
    // CSC: (row, val) at floats [CSC_OFF, CSC_OFF+2*CAP) of output row c
    s = atomicAdd(&g_csc_cnt[c4.x], 1);
    if (s < CAP) *(float2*)(out + (size_t)c4.x * N_NODES + CSC_OFF + 2 * s) = make_float2(__int_as_float(r4.x), v4.x);
    s = atomicAdd(&g_csc_cnt[c4.y], 1);
    if (s < CAP) *(float2*)(out + (size_t)c4.y * N_NODES + CSC_OFF + 2 * s) = make_float2(__int_as_float(r4.y), v4.y);
    s = atomicAdd(&g_csc_cnt[c4.z], 1);
    if (s < CAP) *(float2*)(out + (size_t)c4.z * N_NODES + CSC_OFF + 2 * s) = make_float2(__int_as_float(r4.z), v4.z);
    s = atomicAdd(&g_csc_cnt[c4.w], 1);
    if (s < CAP) *(float2*)(out + (size_t)c4.w * N_NODES + CSC_OFF + 2 * s) = make_float2(__int_as_float(r4.w), v4.w);
}

// Atomic-free gather rounds: W[c] = sum_e v_e * relu(R[row_e] - d[row_e]).
// 8 lanes per column (R9's winning configuration).
__global__ void __launch_bounds__(FBLOCK, 1)
k_rounds(const float* __restrict__ demands,
         const float* __restrict__ out)
{
    __shared__ float s_adj[N_NODES];          // 32 KB
    const int tid = blockIdx.x * FBLOCK + threadIdx.x;

    const int col  = tid >> 3;                // 0..8191
    const int lane = tid & 7;
    const int ncol = min(g_csc_cnt[col], CAP);
    const float2* ep = (const float2*)(out + (size_t)col * N_NODES + CSC_OFF);

    // it reads R = inflow_{it+1}, writes W = inflow_{it+2}; g_buf[0] is zero
    for (int it = 0; it < ROUNDS; ++it) {
        const float* R = g_buf[it & 1];
        float*       W = g_buf[(it + 1) & 1];

        // adj_{it+1} into smem (coalesced per block)
        for (int i = threadIdx.x; i < N_NODES; i += FBLOCK)
            s_adj[i] = fmaxf(ldcg_f(&R[i]) - __ldg(&demands[i]), 0.0f);
        __syncthreads();

        // gather this column's edges (bucket is immutable -> L1-resident
        // after round 1)
        float acc = 0.0f;
        for (int e = lane; e < ncol; e += 8) {
            float2 p = __ldg(ep + e);
            acc += p.y * s_adj[__float_as_int(p.x)];
        }
        acc += __shfl_xor_sync(0xffffffffu, acc, 4, 8);
        acc += __shfl_xor_sync(0xffffffffu, acc, 2, 8);
        acc += __shfl_xor_sync(0xffffffffu, acc, 1, 8);
        if (lane == 0) W[col] = acc;          // each node written exactly once

        if (it < ROUNDS - 1) grid_barrier(it);
        // last round: kernel boundary is the sync; inflow_10 = g_buf[1]
    }
}

// One block per output row: stage CSR bucket, build row in smem, stream out.
__global__ void __launch_bounds__(RBLOCK)
k_rows(const float* __restrict__ demands,
       float*       __restrict__ out)
{
    __shared__ float  srow[N_NODES];          // 32 KB
    __shared__ float2 sbuck[CAP];             // 1 KB
    const int row = blockIdx.x;

    if (row == 0 && threadIdx.x < 16)         // reset barriers for next replay
        g_bar[threadIdx.x] = 0u;

    const int n = min(g_csr_cnt[row], CAP);
    const float* rowp = out + (size_t)row * N_NODES;

    for (int e = threadIdx.x; e < n; e += RBLOCK)
        sbuck[e] = *(const float2*)(rowp + 2 * e);
    for (int i = threadIdx.x; i < N_NODES; i += RBLOCK)
        srow[i] = 0.0f;
    __syncthreads();

    // adj_10[row] = relu(inflow_10[row] - d[row]);  inflow_10 = g_buf[1]
    const float a = fmaxf(g_buf[1][row] - __ldg(&demands[row]), 0.0f);

    for (int e = threadIdx.x; e < n; e += RBLOCK)
        atomicAdd(&srow[__float_as_int(sbuck[e].x)], sbuck[e].y * a);
    __syncthreads();

    float4*       dst = (float4*)(out + (size_t)row * N_NODES);
    const float4* src = (const float4*)srow;
    for (int i = threadIdx.x; i < N_NODES / 4; i += RBLOCK)
        dst[i] = src[i];
}

// Restore the zeroed state for the next replay (off the critical path).
__global__ void __launch_bounds__(RBLOCK)
k_clean()
{
    int i = blockIdx.x * RBLOCK + threadIdx.x;
    if (i < N_NODES) {
        g_csr_cnt[i] = 0;
        g_csc_cnt[i] = 0;
        g_buf[0][i]  = 0.0f;                  // inflow_1 = 0 for next pass
    }
}

extern "C" void kernel_launch(void* const* d_in, const int* in_sizes, int n_in,
                              void* d_out, int out_size) {
    const float* values  = (const float*)d_in[0];
    const float* demands = (const float*)d_in[1];
    const int*   rows    = (const int*)d_in[2];
    const int*   cols    = (const int*)d_in[3];
    float*       out     = (float*)d_out;

    const int E  = in_sizes[0];   // 262144
    const int e4 = E / 4;         // 65536

    k_bucket<<<FGRID, FBLOCK>>>(rows, cols, values, out, e4);
    k_rounds<<<FGRID, FBLOCK>>>(demands, out);
    k_rows<<<N_NODES, RBLOCK>>>(demands, out);
    k_clean<<<(N_NODES + RBLOCK - 1) / RBLOCK, RBLOCK>>>();
}

// round 12
// speedup vs baseline: 2.2528x; 1.1640x over previous
#include <cuda_runtime.h>
#include <cuda_bf16.h>

#define N_NODES  8192
#define ROUNDS   9            // rounds producing inflow_2 .. inflow_10
#define CAP      128          // bucket capacity (Poisson(32): P(>127) ~ 1e-40)
#define CSC_OFF  4096         // float offset of CSC bucket inside an output row
#define FB       64           // flow blocks (FB*1024 == e4 == 65536)
#define GRID     148          // one wave
#define FBLOCK   1024
#define ZB       (GRID - FB)  // 84 zero-stream blocks
#define ROW4     (N_NODES / 4)        // 2048 float4 per row
#define FINAL_T  128

// small persistent scratch (zeroed at module load; k_final restores zeroed
// state each pass -> deterministic graph replays)
__device__ unsigned int g_bar[16];          // monotonic barrier counters
__device__ float        g_buf[2][N_NODES];  // double-buffered inflow
__device__ int          g_csr_cnt[N_NODES];
__device__ int          g_csc_cnt[N_NODES];

__device__ __forceinline__ float ldcg_f(const float* p) {
    float v;
    asm volatile("ld.global.cg.f32 %0, [%1];" : "=f"(v) : "l"(p));
    return v;
}

// barrier among the FB flow blocks (monotonic counters; reset by k_final)
__device__ __forceinline__ void flow_barrier(int b) {
    __syncthreads();
    if (threadIdx.x == 0) {
        __threadfence();
        atomicAdd(&g_bar[b], 1u);
        volatile unsigned int* p = &g_bar[b];
        while (*p < FB) __nanosleep(32);
        __threadfence();
    }
    __syncthreads();
}

__global__ void __launch_bounds__(FBLOCK, 1)
k_mega(const int*   __restrict__ rows,
       const int*   __restrict__ cols,
       const float* __restrict__ values,
       const float* __restrict__ demands,
       float*       __restrict__ out,
       int e4)
{
    if (blockIdx.x >= FB) {
        // ── zero workers: 240MB of zeros, skipping the per-row bucket
        //    regions (float4 [0,64) CSR and [1024,1088) CSC). __stcs keeps
        //    the stream from evicting the dirty bucket lines out of L2. ──
        const float4 z = make_float4(0.f, 0.f, 0.f, 0.f);
        for (int r = blockIdx.x - FB; r < N_NODES; r += ZB) {
            float4* rowp = (float4*)(out + (size_t)r * N_NODES);
            #pragma unroll
            for (int k = 0; k < 2; ++k) {
                int i = threadIdx.x + k * FBLOCK;        // 0..2047
                if (i < 1920) {
                    int idx = (i < 960) ? (64 + i) : (1088 + (i - 960));
                    __stcs(rowp + idx, z);
                }
            }
        }
        return;
    }

    // ───────────── flow blocks: bucket, then 9 gather rounds ─────────────
    __shared__ float s_adj[N_NODES];          // 32 KB
    const int tid = blockIdx.x * FBLOCK + threadIdx.x;   // 0..65535 == e4

    {   // bucket this thread's 4 edges (counters pre-zeroed by k_final)
        int4   r4 = __ldg(((const int4*)rows)   + tid);
        int4   c4 = __ldg(((const int4*)cols)   + tid);
        float4 v4 = __ldg(((const float4*)values) + tid);
        int s;
        // CSR: (col, val) at floats [0, 2*CAP) of output row r
        s = atomicAdd(&g_csr_cnt[r4.x], 1);
        if (s < CAP) *(float2*)(out + (size_t)r4.x * N_NODES + 2 * s) = make_float2(__int_as_float(c4.x), v4.x);
        s = atomicAdd(&g_csr_cnt[r4.y], 1);
        if (s < CAP) *(float2*)(out + (size_t)r4.y * N_NODES + 2 * s) = make_float2(__int_as_float(c4.y), v4.y);
        s = atomicAdd(&g_csr_cnt[r4.z], 1);
        if (s < CAP) *(float2*)(out + (size_t)r4.z * N_NODES + 2 * s) = make_float2(__int_as_float(c4.z), v4.z);
        s = atomicAdd(&g_csr_cnt[r4.w], 1);
        if (s < CAP) *(float2*)(out + (size_t)r4.w * N_NODES + 2 * s) = make_float2(__int_as_float(c4.w), v4.w);
        // CSC: (row, val) at floats [CSC_OFF, CSC_OFF+2*CAP) of output row c
        s = atomicAdd(&g_csc_cnt[c4.x], 1);
        if (s < CAP) *(float2*)(out + (size_t)c4.x * N_NODES + CSC_OFF + 2 * s) = make_float2(__int_as_float(r4.x), v4.x);
        s = atomicAdd(&g_csc_cnt[c4.y], 1);
        if (s < CAP) *(float2*)(out + (size_t)c4.y * N_NODES + CSC_OFF + 2 * s) = make_float2(__int_as_float(r4.y), v4.y);
        s = atomicAdd(&g_csc_cnt[c4.z], 1);
        if (s < CAP) *(float2*)(out + (size_t)c4.z * N_NODES + CSC_OFF + 2 * s) = make_float2(__int_as_float(r4.z), v4.z);
        s = atomicAdd(&g_csc_cnt[c4.w], 1);
        if (s < CAP) *(float2*)(out + (size_t)c4.w * N_NODES + CSC_OFF + 2 * s) = make_float2(__int_as_float(r4.w), v4.w);
    }

    flow_barrier(0);                          // all buckets complete

    // 8 lanes per column (R9's winning configuration)
    const int col  = tid >> 3;                // 0..8191
    const int lane = tid & 7;
    const int ncol = min(g_csc_cnt[col], CAP);
    const float2* ep = (const float2*)(out + (size_t)col * N_NODES + CSC_OFF);

    // it reads R = inflow_{it+1}, writes W = inflow_{it+2}; g_buf[0] is zero
    for (int it = 0; it < ROUNDS; ++it) {
        const float* R = g_buf[it & 1];
        float*       W = g_buf[(it + 1) & 1];

        for (int i = threadIdx.x; i < N_NODES; i += FBLOCK)
            s_adj[i] = fmaxf(ldcg_f(&R[i]) - __ldg(&demands[i]), 0.0f);
        __syncthreads();

        float acc = 0.0f;
        for (int e = lane; e < ncol; e += 8) {
            float2 p = __ldg(ep + e);         // L1-resident after round 1
            acc += p.y * s_adj[__float_as_int(p.x)];
        }
        acc += __shfl_xor_sync(0xffffffffu, acc, 4, 8);
        acc += __shfl_xor_sync(0xffffffffu, acc, 2, 8);
        acc += __shfl_xor_sync(0xffffffffu, acc, 1, 8);
        if (lane == 0) W[col] = acc;          // each node written exactly once

        if (it < ROUNDS - 1) flow_barrier(1 + it);
        // last round: kernel boundary is the sync; inflow_10 = g_buf[1]
    }
}

// Per row: stage CSR bucket, zero the two bucket regions, scatter the ~32
// nonzeros (row-private atomics for duplicate cols), and do ALL cleanup.
__global__ void __launch_bounds__(FINAL_T)
k_final(const float* __restrict__ demands,
        float*       __restrict__ out)
{
    __shared__ float2 sbuck[CAP];             // 1 KB
    const int row = blockIdx.x;
    float* rowp = out + (size_t)row * N_NODES;

    const int n = min(g_csr_cnt[row], CAP);
    for (int e = threadIdx.x; e < n; e += FINAL_T)
        sbuck[e] = *(const float2*)(rowp + 2 * e);
    __syncthreads();

    // zero the bucket regions: float4 [0,64) and [1024,1088)
    const float4 z = make_float4(0.f, 0.f, 0.f, 0.f);
    if (threadIdx.x < 64) {
        ((float4*)rowp)[threadIdx.x]        = z;
        ((float4*)rowp)[1024 + threadIdx.x] = z;
    }
    __syncthreads();

    // adj_10[row] = relu(inflow_10[row] - d[row]);  inflow_10 = g_buf[1]
    const float a = fmaxf(g_buf[1][row] - __ldg(&demands[row]), 0.0f);

    for (int e = threadIdx.x; e < n; e += FINAL_T) {
        float2 p = sbuck[e];
        atomicAdd(rowp + __float_as_int(p.x), p.y * a);   // row-private
    }

    // cleanup for the next graph replay
    if (threadIdx.x == 0) {
        g_csr_cnt[row] = 0;
        g_csc_cnt[row] = 0;
        g_buf[0][row]  = 0.0f;
    }
    if (row == 0 && threadIdx.x < 16)
        g_bar[threadIdx.x] = 0u;
}

extern "C" void kernel_launch(void* const* d_in, const int* in_sizes, int n_in,
                              void* d_out, int out_size) {
    const float* values  = (const float*)d_in[0];
    const float* demands = (const float*)d_in[1];
    const int*   rows    = (const int*)d_in[2];
    const int*   cols    = (const int*)d_in[3];
    float*       out     = (float*)d_out;

    const int E  = in_sizes[0];   // 262144
    const int e4 = E / 4;         // 65536

    k_mega<<<GRID, FBLOCK>>>(rows, cols, values, demands, out, e4);
    k_final<<<N_NODES, FINAL_T>>>(demands, out);
}